// round 1
// baseline (speedup 1.0000x reference)
#include <cuda_runtime.h>
#include <cstdint>

#define N0    512000
#define IN_F  128
#define HID   256
#define OUT_F 64
#define NN1   20480
#define NN2   2048
#define NE1   512000
#define NE2   20480
#define EPSV  1e-4f

// ---------------- device scratch (no allocation allowed) ----------------
__device__ float    g_alpha1[N0];
__device__ uint4    g_mask1[N0];
__device__ unsigned g_cnt1[NN1];
__device__ unsigned g_off1[NN1 + 1];
__device__ unsigned g_cur1[NN1];
__device__ int      g_srcs1[NE1];
__device__ float    g_agg1[NN1 * IN_F];
__device__ float    g_h[NN1 * HID];
__device__ float    g_alpha2[NN1];
__device__ unsigned g_mask2[NN1 * 8];
__device__ unsigned g_cnt2[NN2];
__device__ unsigned g_off2[NN2 + 1];
__device__ unsigned g_cur2[NN2];
__device__ int      g_srcs2[NE2];
__device__ float    g_agg2[NN2 * HID];
__device__ float    g_bt1[IN_F * HID];    // w_hat_rel1 transposed: [k=128][n=256]
__device__ float    g_mroot1[HID];
__device__ uint4    g_wmask1[HID];
__device__ float    g_bt2[HID * OUT_F];   // w_hat_rel2 transposed: [256][64]
__device__ float    g_mroot2[OUT_F];
__device__ unsigned g_wmask2[OUT_F * 8];

// ---------------- helpers ----------------
__device__ __forceinline__ float warp_sum(float v) {
#pragma unroll
    for (int o = 16; o; o >>= 1) v += __shfl_xor_sync(0xffffffffu, v, o);
    return v;
}
__device__ __forceinline__ float warp_max(float v) {
#pragma unroll
    for (int o = 16; o; o >>= 1) v = fmaxf(v, __shfl_xor_sync(0xffffffffu, v, o));
    return v;
}
__device__ __forceinline__ unsigned long long bcast2(float a) {
    unsigned long long r;
    asm("mov.b64 %0, {%1, %1};" : "=l"(r) : "f"(a));
    return r;
}
__device__ __forceinline__ void fma2(unsigned long long& c, unsigned long long a, unsigned long long b) {
    asm("fma.rn.f32x2 %0, %1, %2, %0;" : "+l"(c) : "l"(a), "l"(b));
}
__device__ __forceinline__ void unpack2(unsigned long long v, float& lo, float& hi) {
    asm("mov.b64 {%0, %1}, %2;" : "=f"(lo), "=f"(hi) : "l"(v));
}

// ---------------- weight prep ----------------
// 640 warps total: [0,256) w_rel1 rows, [256,512) w_root1 rows,
// [512,576) w_rel2 rows, [576,640) w_root2 rows.
__global__ __launch_bounds__(128) void prep_weights(
    const float* __restrict__ wr1, const float* __restrict__ wroot1,
    const float* __restrict__ wr2, const float* __restrict__ wroot2)
{
    int w = (blockIdx.x * blockDim.x + threadIdx.x) >> 5;
    int L = threadIdx.x & 31;
    if (w < HID) {
        int k = w;
        const float* p = wr1 + (size_t)k * IN_F;
        float v[4]; float s = 0.f;
#pragma unroll
        for (int q = 0; q < 4; q++) { v[q] = p[L + 32 * q]; s += fabsf(v[q]); }
        s = warp_sum(s);
        float m = s * (1.f / IN_F);
#pragma unroll
        for (int q = 0; q < 4; q++) {
            int j = L + 32 * q;
            float val = v[q] > 0.f ? m : (v[q] < 0.f ? -m : 0.f);
            g_bt1[j * HID + k] = val;
        }
    } else if (w < 2 * HID) {
        int k = w - HID;
        const float* p = wroot1 + (size_t)k * IN_F;
        float v[4]; float s = 0.f;
#pragma unroll
        for (int q = 0; q < 4; q++) { v[q] = p[L + 32 * q]; s += fabsf(v[q]); }
        s = warp_sum(s);
        unsigned b[4];
#pragma unroll
        for (int q = 0; q < 4; q++) b[q] = __ballot_sync(0xffffffffu, v[q] > 0.f);
        if (L == 0) {
            g_mroot1[k] = s * (1.f / IN_F);
            g_wmask1[k] = make_uint4(b[0], b[1], b[2], b[3]);
        }
    } else if (w < 2 * HID + OUT_F) {
        int k = w - 2 * HID;
        const float* p = wr2 + (size_t)k * HID;
        float v[8]; float s = 0.f;
#pragma unroll
        for (int q = 0; q < 8; q++) { v[q] = p[L + 32 * q]; s += fabsf(v[q]); }
        s = warp_sum(s);
        float m = s * (1.f / HID);
#pragma unroll
        for (int q = 0; q < 8; q++) {
            int j = L + 32 * q;
            float val = v[q] > 0.f ? m : (v[q] < 0.f ? -m : 0.f);
            g_bt2[j * OUT_F + k] = val;
        }
    } else if (w < 2 * HID + 2 * OUT_F) {
        int k = w - 2 * HID - OUT_F;
        const float* p = wroot2 + (size_t)k * HID;
        float v[8]; float s = 0.f;
#pragma unroll
        for (int q = 0; q < 8; q++) { v[q] = p[L + 32 * q]; s += fabsf(v[q]); }
        s = warp_sum(s);
        unsigned b[8];
#pragma unroll
        for (int q = 0; q < 8; q++) b[q] = __ballot_sync(0xffffffffu, v[q] > 0.f);
        if (L == 0) {
            g_mroot2[k] = s * (1.f / HID);
#pragma unroll
            for (int q = 0; q < 8; q++) g_wmask2[k * 8 + q] = b[q];
        }
    }
}

// ---------------- zero counters ----------------
__global__ void zero_counts() {
    int i = blockIdx.x * blockDim.x + threadIdx.x;
    if (i < NN1) g_cnt1[i] = 0u;
    if (i < NN2) g_cnt2[i] = 0u;
}

// ---------------- bin_act over 128 cols (x) ----------------
__global__ __launch_bounds__(256) void binact1_kernel(const float* __restrict__ x) {
    int row = blockIdx.x * 8 + (threadIdx.x >> 5);
    if (row >= N0) return;
    int L = threadIdx.x & 31;
    const float* xr = x + (size_t)row * IN_F;
    float v0 = xr[L], v1 = xr[L + 32], v2 = xr[L + 64], v3 = xr[L + 96];
    float mu = warp_sum(v0 + v1 + v2 + v3) * (1.f / 128.f);
    float d0 = v0 - mu, d1 = v1 - mu, d2 = v2 - mu, d3 = v3 - mu;
    float l1 = warp_sum(fabsf(d0) + fabsf(d1) + fabsf(d2) + fabsf(d3));
    float sq = warp_sum(d0 * d0 + d1 * d1 + d2 * d2 + d3 * d3);
    float sd = sqrtf(sq * (1.f / 127.f));
    float a = (l1 * (1.f / 128.f)) / (sd + EPSV);
    unsigned b0 = __ballot_sync(0xffffffffu, d0 > 0.f);
    unsigned b1 = __ballot_sync(0xffffffffu, d1 > 0.f);
    unsigned b2 = __ballot_sync(0xffffffffu, d2 > 0.f);
    unsigned b3 = __ballot_sync(0xffffffffu, d3 > 0.f);
    if (L == 0) {
        g_alpha1[row] = a;
        g_mask1[row] = make_uint4(b0, b1, b2, b3);
    }
}

// ---------------- bin_act over 256 cols (h) ----------------
__global__ __launch_bounds__(256) void binact2_kernel() {
    int row = blockIdx.x * 8 + (threadIdx.x >> 5);
    if (row >= NN1) return;
    int L = threadIdx.x & 31;
    const float* xr = g_h + (size_t)row * HID;
    float v[8]; float s = 0.f;
#pragma unroll
    for (int q = 0; q < 8; q++) { v[q] = xr[L + 32 * q]; s += v[q]; }
    float mu = warp_sum(s) * (1.f / 256.f);
    float l1 = 0.f, sq = 0.f;
    float d[8];
#pragma unroll
    for (int q = 0; q < 8; q++) { d[q] = v[q] - mu; l1 += fabsf(d[q]); sq += d[q] * d[q]; }
    l1 = warp_sum(l1); sq = warp_sum(sq);
    float sd = sqrtf(sq * (1.f / 255.f));
    float a = (l1 * (1.f / 256.f)) / (sd + EPSV);
    unsigned b[8];
#pragma unroll
    for (int q = 0; q < 8; q++) b[q] = __ballot_sync(0xffffffffu, d[q] > 0.f);
    if (L == 0) {
        g_alpha2[row] = a;
#pragma unroll
        for (int q = 0; q < 8; q++) g_mask2[(size_t)row * 8 + q] = b[q];
    }
}

// ---------------- histogram / scan / placement (counting sort by dst) -------
__global__ void hist_kernel(const int* __restrict__ dst, int E, int layer) {
    int i = blockIdx.x * blockDim.x + threadIdx.x;
    if (i >= E) return;
    unsigned* cnt = layer ? g_cnt2 : g_cnt1;
    atomicAdd(&cnt[dst[i]], 1u);
}

__global__ __launch_bounds__(1024) void scan_kernel(int layer) {
    const unsigned* cnt = layer ? g_cnt2 : g_cnt1;
    unsigned* off = layer ? g_off2 : g_off1;
    unsigned* cur = layer ? g_cur2 : g_cur1;
    int n = layer ? NN2 : NN1;
    __shared__ unsigned ss[1024];
    int t = threadIdx.x;
    int per = (n + 1023) >> 10;
    int s0 = t * per;
    unsigned loc = 0;
    for (int i = 0; i < per; i++) { int idx = s0 + i; if (idx < n) loc += cnt[idx]; }
    ss[t] = loc;
    __syncthreads();
    for (int o = 1; o < 1024; o <<= 1) {
        unsigned v = (t >= o) ? ss[t - o] : 0u;
        __syncthreads();
        ss[t] += v;
        __syncthreads();
    }
    unsigned run = (t > 0) ? ss[t - 1] : 0u;
    for (int i = 0; i < per; i++) {
        int idx = s0 + i;
        if (idx < n) { off[idx] = run; cur[idx] = run; run += cnt[idx]; }
    }
    if (t == 1023) off[n] = ss[1023];
}

__global__ void place_kernel(const int* __restrict__ dst, const int* __restrict__ src,
                             int E, int layer) {
    int i = blockIdx.x * blockDim.x + threadIdx.x;
    if (i >= E) return;
    unsigned* cur = layer ? g_cur2 : g_cur1;
    int* srcs = layer ? g_srcs2 : g_srcs1;
    unsigned p = atomicAdd(&cur[dst[i]], 1u);
    srcs[p] = src[i];
}

// ---------------- layer-1 aggregation: warp per dst ----------------
__global__ __launch_bounds__(256) void agg1_kernel() {
    int d = (blockIdx.x * blockDim.x + threadIdx.x) >> 5;
    if (d >= NN1) return;
    int L = threadIdx.x & 31;
    unsigned beg = g_off1[d], c = g_cnt1[d];
    float a0 = 0.f, a1 = 0.f, a2 = 0.f, a3 = 0.f;
    for (unsigned e = beg; e < beg + c; e++) {
        int s = g_srcs1[e];
        uint4 m = g_mask1[s];
        float al = g_alpha1[s];
        a0 += ((m.x >> L) & 1u) ? al : -al;
        a1 += ((m.y >> L) & 1u) ? al : -al;
        a2 += ((m.z >> L) & 1u) ? al : -al;
        a3 += ((m.w >> L) & 1u) ? al : -al;
    }
    float inv = 1.f / (float)(c == 0u ? 1u : c);
    float* o = g_agg1 + (size_t)d * IN_F;
    o[L] = a0 * inv; o[L + 32] = a1 * inv; o[L + 64] = a2 * inv; o[L + 96] = a3 * inv;
}

// ---------------- layer-2 aggregation: warp per dst ----------------
__global__ __launch_bounds__(256) void agg2_kernel() {
    int d = (blockIdx.x * blockDim.x + threadIdx.x) >> 5;
    if (d >= NN2) return;
    int L = threadIdx.x & 31;
    unsigned beg = g_off2[d], c = g_cnt2[d];
    float acc[8];
#pragma unroll
    for (int q = 0; q < 8; q++) acc[q] = 0.f;
    for (unsigned e = beg; e < beg + c; e++) {
        int s = g_srcs2[e];
        const uint4* mp = (const uint4*)(g_mask2 + (size_t)s * 8);
        uint4 ma = mp[0], mb = mp[1];
        float al = g_alpha2[s];
        unsigned mw[8] = {ma.x, ma.y, ma.z, ma.w, mb.x, mb.y, mb.z, mb.w};
#pragma unroll
        for (int q = 0; q < 8; q++) acc[q] += ((mw[q] >> L) & 1u) ? al : -al;
    }
    float inv = 1.f / (float)(c == 0u ? 1u : c);
    float* o = g_agg2 + (size_t)d * HID;
#pragma unroll
    for (int q = 0; q < 8; q++) o[L + 32 * q] = acc[q] * inv;
}

// ---------------- layer-1 GEMM + popc root + bias + relu ----------------
// C[20480x256] = agg1 @ bt1 (+ root + biases), relu -> g_h
#define GBM 128
#define GBN 128
#define GBK 32
__global__ __launch_bounds__(256) void gemm1_kernel(const float* __restrict__ brel,
                                                    const float* __restrict__ broot) {
    __shared__ float As[GBM][GBK + 4];   // row-major, stride 36 floats (144B, 16B aligned)
    __shared__ float Bs[GBK][GBN + 4];
    int tid = threadIdx.x;
    int tx = tid & 15, ty = tid >> 4;
    int bm = blockIdx.x * GBM;
    int bn = blockIdx.y * GBN;
    unsigned long long acc[8][4];
#pragma unroll
    for (int i = 0; i < 8; i++)
#pragma unroll
        for (int j = 0; j < 4; j++) acc[i][j] = 0ull;

    for (int k0 = 0; k0 < IN_F; k0 += GBK) {
#pragma unroll
        for (int r = 0; r < 4; r++) {
            int f = tid + r * 256;        // 1024 float4s
            int row = f >> 3, kq = f & 7;
            float4 v = *(const float4*)(g_agg1 + (size_t)(bm + row) * IN_F + k0 + kq * 4);
            *(float4*)&As[row][kq * 4] = v;
        }
#pragma unroll
        for (int r = 0; r < 4; r++) {
            int g = tid + r * 256;
            int kk = g >> 5, nq = g & 31;
            *(float4*)&Bs[kk][nq * 4] =
                *(const float4*)(g_bt1 + (size_t)(k0 + kk) * HID + bn + nq * 4);
        }
        __syncthreads();
#pragma unroll
        for (int kk = 0; kk < GBK; kk++) {
            float a[8];
#pragma unroll
            for (int i = 0; i < 8; i++) a[i] = As[ty * 8 + i][kk];
            unsigned long long b2[4];
            const unsigned long long* bp = (const unsigned long long*)&Bs[kk][tx * 8];
            b2[0] = bp[0]; b2[1] = bp[1]; b2[2] = bp[2]; b2[3] = bp[3];
#pragma unroll
            for (int i = 0; i < 8; i++) {
                unsigned long long ad = bcast2(a[i]);
                fma2(acc[i][0], ad, b2[0]);
                fma2(acc[i][1], ad, b2[1]);
                fma2(acc[i][2], ad, b2[2]);
                fma2(acc[i][3], ad, b2[3]);
            }
        }
        __syncthreads();
    }

    // epilogue
#pragma unroll
    for (int i = 0; i < 8; i++) {
        int gm = bm + ty * 8 + i;
        float al = g_alpha1[gm];
        uint4 mx = g_mask1[gm];
        float out[8];
#pragma unroll
        for (int j = 0; j < 4; j++) {
            float lo, hi;
            unpack2(acc[i][j], lo, hi);
            int c0 = bn + tx * 8 + 2 * j;
            int c1 = c0 + 1;
            uint4 w0 = g_wmask1[c0];
            uint4 w1 = g_wmask1[c1];
            int p0 = __popc(mx.x ^ w0.x) + __popc(mx.y ^ w0.y) +
                     __popc(mx.z ^ w0.z) + __popc(mx.w ^ w0.w);
            int p1 = __popc(mx.x ^ w1.x) + __popc(mx.y ^ w1.y) +
                     __popc(mx.z ^ w1.z) + __popc(mx.w ^ w1.w);
            float v0 = lo + brel[c0] + broot[c0] + al * g_mroot1[c0] * (float)(128 - 2 * p0);
            float v1 = hi + brel[c1] + broot[c1] + al * g_mroot1[c1] * (float)(128 - 2 * p1);
            out[2 * j] = fmaxf(v0, 0.f);
            out[2 * j + 1] = fmaxf(v1, 0.f);
        }
        float* hp = g_h + (size_t)gm * HID + bn + tx * 8;
        *(float4*)hp = make_float4(out[0], out[1], out[2], out[3]);
        *(float4*)(hp + 4) = make_float4(out[4], out[5], out[6], out[7]);
    }
}

// ---------------- final: GEMM2 + popc root + log_softmax ----------------
__global__ __launch_bounds__(256) void final_kernel(const float* __restrict__ brel2,
                                                    const float* __restrict__ broot2,
                                                    float* __restrict__ out) {
    __shared__ float sa[8][HID];
    int w = threadIdx.x >> 5, L = threadIdx.x & 31;
    int row = blockIdx.x * 8 + w;
#pragma unroll
    for (int q = 0; q < 8; q++) sa[w][L + 32 * q] = g_agg2[(size_t)row * HID + L + 32 * q];
    __syncwarp();
    int c0 = L, c1 = L + 32;
    float acc0 = 0.f, acc1 = 0.f;
#pragma unroll 8
    for (int j = 0; j < HID; j++) {
        float a = sa[w][j];
        acc0 = fmaf(a, g_bt2[j * OUT_F + c0], acc0);
        acc1 = fmaf(a, g_bt2[j * OUT_F + c1], acc1);
    }
    const uint4* mp = (const uint4*)(g_mask2 + (size_t)row * 8);
    uint4 ma = mp[0], mb = mp[1];
    float al = g_alpha2[row];
    const unsigned* w0 = g_wmask2 + c0 * 8;
    const unsigned* w1 = g_wmask2 + c1 * 8;
    int p0 = __popc(ma.x ^ w0[0]) + __popc(ma.y ^ w0[1]) + __popc(ma.z ^ w0[2]) +
             __popc(ma.w ^ w0[3]) + __popc(mb.x ^ w0[4]) + __popc(mb.y ^ w0[5]) +
             __popc(mb.z ^ w0[6]) + __popc(mb.w ^ w0[7]);
    int p1 = __popc(ma.x ^ w1[0]) + __popc(ma.y ^ w1[1]) + __popc(ma.z ^ w1[2]) +
             __popc(ma.w ^ w1[3]) + __popc(mb.x ^ w1[4]) + __popc(mb.y ^ w1[5]) +
             __popc(mb.z ^ w1[6]) + __popc(mb.w ^ w1[7]);
    float v0 = acc0 + brel2[c0] + broot2[c0] + al * g_mroot2[c0] * (float)(256 - 2 * p0);
    float v1 = acc1 + brel2[c1] + broot2[c1] + al * g_mroot2[c1] * (float)(256 - 2 * p1);
    float mx = warp_max(fmaxf(v0, v1));
    float s = warp_sum(expf(v0 - mx) + expf(v1 - mx));
    float lse = mx + logf(s);
    out[(size_t)row * OUT_F + c0] = v0 - lse;
    out[(size_t)row * OUT_F + c1] = v1 - lse;
}

// ---------------- launcher ----------------
extern "C" void kernel_launch(void* const* d_in, const int* in_sizes, int n_in,
                              void* d_out, int out_size) {
    const float* x       = (const float*)d_in[0];
    const int*   src1    = (const int*)d_in[1];
    const int*   dst1    = (const int*)d_in[2];
    const int*   src2    = (const int*)d_in[3];
    const int*   dst2    = (const int*)d_in[4];
    const float* w_rel1  = (const float*)d_in[5];
    const float* b_rel1  = (const float*)d_in[6];
    const float* w_root1 = (const float*)d_in[7];
    const float* b_root1 = (const float*)d_in[8];
    const float* w_rel2  = (const float*)d_in[9];
    const float* b_rel2  = (const float*)d_in[10];
    const float* w_root2 = (const float*)d_in[11];
    const float* b_root2 = (const float*)d_in[12];
    float* out = (float*)d_out;

    prep_weights<<<160, 128>>>(w_rel1, w_root1, w_rel2, w_root2);
    zero_counts<<<(NN1 + 255) / 256, 256>>>();
    binact1_kernel<<<N0 / 8, 256>>>(x);
    hist_kernel<<<(NE1 + 255) / 256, 256>>>(dst1, NE1, 0);
    scan_kernel<<<1, 1024>>>(0);
    place_kernel<<<(NE1 + 255) / 256, 256>>>(dst1, src1, NE1, 0);
    agg1_kernel<<<(NN1 * 32 + 255) / 256, 256>>>();
    gemm1_kernel<<<dim3(NN1 / GBM, HID / GBN), 256>>>(b_rel1, b_root1);
    binact2_kernel<<<NN1 / 8, 256>>>();
    hist_kernel<<<(NE2 + 255) / 256, 256>>>(dst2, NE2, 1);
    scan_kernel<<<1, 1024>>>(1);
    place_kernel<<<(NE2 + 255) / 256, 256>>>(dst2, src2, NE2, 1);
    agg2_kernel<<<(NN2 * 32 + 255) / 256, 256>>>();
    final_kernel<<<NN2 / 8, 256>>>(b_rel2, b_root2, out);
    (void)in_sizes; (void)n_in; (void)out_size;
}

// round 2
// speedup vs baseline: 1.1854x; 1.1854x over previous
#include <cuda_runtime.h>
#include <cstdint>

#define N0    512000
#define IN_F  128
#define HID   256
#define OUT_F 64
#define NN1   20480
#define NN2   2048
#define NE1   512000
#define NE2   20480
#define EPSV  1e-4f

// ---------------- device scratch ----------------
__device__ float    g_alpha1[N0];
__device__ uint4    g_mask1[N0];
__device__ unsigned g_cnt1[NN1];
__device__ unsigned g_off1[NN1 + 1];
__device__ unsigned g_cur1[NN1];
__device__ int      g_srcs1[NE1];
__device__ float    g_agg1[NN1 * IN_F];
__device__ float    g_alpha2[NN1];
__device__ unsigned g_mask2[NN1 * 8];
__device__ unsigned g_cnt2[NN2];
__device__ unsigned g_off2[NN2 + 1];
__device__ unsigned g_cur2[NN2];
__device__ int      g_srcs2[NE2];
__device__ float    g_bt1[IN_F * HID];    // w_hat_rel1 transposed: [k=128][n=256]
__device__ float    g_mroot1[HID];
__device__ uint4    g_wmask1[HID];
__device__ float    g_bsum1[HID];
__device__ float    g_bt2[HID * OUT_F];   // [256][64]
__device__ float    g_mroot2[OUT_F];
__device__ unsigned g_wmask2[OUT_F * 8];
__device__ float    g_bsum2[OUT_F];

// ---------------- helpers ----------------
__device__ __forceinline__ float warp_sum(float v) {
#pragma unroll
    for (int o = 16; o; o >>= 1) v += __shfl_xor_sync(0xffffffffu, v, o);
    return v;
}
__device__ __forceinline__ float warp_max(float v) {
#pragma unroll
    for (int o = 16; o; o >>= 1) v = fmaxf(v, __shfl_xor_sync(0xffffffffu, v, o));
    return v;
}
__device__ __forceinline__ unsigned long long bcast2(float a) {
    unsigned long long r;
    asm("mov.b64 %0, {%1, %1};" : "=l"(r) : "f"(a));
    return r;
}
__device__ __forceinline__ void fma2(unsigned long long& c, unsigned long long a, unsigned long long b) {
    asm("fma.rn.f32x2 %0, %1, %2, %0;" : "+l"(c) : "l"(a), "l"(b));
}
__device__ __forceinline__ void unpack2(unsigned long long v, float& lo, float& hi) {
    asm("mov.b64 {%0, %1}, %2;" : "=f"(lo), "=f"(hi) : "l"(v));
}
__device__ __forceinline__ int popc4(uint4 a, uint4 b) {
    return __popc(a.x ^ b.x) + __popc(a.y ^ b.y) + __popc(a.z ^ b.z) + __popc(a.w ^ b.w);
}

// ---------------- weight prep + counter zero + bias sums ----------------
// 160 blocks x 128 threads = 20480 threads = 640 warps.
__global__ __launch_bounds__(128) void prep_zero(
    const float* __restrict__ wr1, const float* __restrict__ wroot1,
    const float* __restrict__ wr2, const float* __restrict__ wroot2,
    const float* __restrict__ brel1, const float* __restrict__ broot1,
    const float* __restrict__ brel2, const float* __restrict__ broot2)
{
    int t = blockIdx.x * 128 + threadIdx.x;   // 0..20479
    g_cnt1[t] = 0u;
    if (t < NN2) g_cnt2[t] = 0u;
    if (t < HID) g_bsum1[t] = brel1[t] + broot1[t];
    if (t < OUT_F) g_bsum2[t] = brel2[t] + broot2[t];

    int w = t >> 5;
    int L = threadIdx.x & 31;
    if (w < HID) {
        int k = w;
        float4 v = *(const float4*)(wr1 + (size_t)k * IN_F + 4 * L);
        float s = warp_sum(fabsf(v.x) + fabsf(v.y) + fabsf(v.z) + fabsf(v.w));
        float m = s * (1.f / IN_F);
        float vv[4] = {v.x, v.y, v.z, v.w};
#pragma unroll
        for (int q = 0; q < 4; q++) {
            int j = 4 * L + q;
            float val = vv[q] > 0.f ? m : (vv[q] < 0.f ? -m : 0.f);
            g_bt1[j * HID + k] = val;
        }
    } else if (w < 2 * HID) {
        int k = w - HID;
        float4 v = *(const float4*)(wroot1 + (size_t)k * IN_F + 4 * L);
        float s = warp_sum(fabsf(v.x) + fabsf(v.y) + fabsf(v.z) + fabsf(v.w));
        unsigned b0 = __ballot_sync(0xffffffffu, v.x > 0.f);
        unsigned b1 = __ballot_sync(0xffffffffu, v.y > 0.f);
        unsigned b2 = __ballot_sync(0xffffffffu, v.z > 0.f);
        unsigned b3 = __ballot_sync(0xffffffffu, v.w > 0.f);
        if (L == 0) {
            g_mroot1[k] = s * (1.f / IN_F);
            g_wmask1[k] = make_uint4(b0, b1, b2, b3);
        }
    } else if (w < 2 * HID + OUT_F) {
        int k = w - 2 * HID;
        float4 u = *(const float4*)(wr2 + (size_t)k * HID + 8 * L);
        float4 v = *(const float4*)(wr2 + (size_t)k * HID + 8 * L + 4);
        float s = warp_sum(fabsf(u.x) + fabsf(u.y) + fabsf(u.z) + fabsf(u.w) +
                           fabsf(v.x) + fabsf(v.y) + fabsf(v.z) + fabsf(v.w));
        float m = s * (1.f / HID);
        float vv[8] = {u.x, u.y, u.z, u.w, v.x, v.y, v.z, v.w};
#pragma unroll
        for (int q = 0; q < 8; q++) {
            int j = 8 * L + q;
            float val = vv[q] > 0.f ? m : (vv[q] < 0.f ? -m : 0.f);
            g_bt2[j * OUT_F + k] = val;
        }
    } else if (w < 2 * HID + 2 * OUT_F) {
        int k = w - 2 * HID - OUT_F;
        float4 u = *(const float4*)(wroot2 + (size_t)k * HID + 8 * L);
        float4 v = *(const float4*)(wroot2 + (size_t)k * HID + 8 * L + 4);
        float s = warp_sum(fabsf(u.x) + fabsf(u.y) + fabsf(u.z) + fabsf(u.w) +
                           fabsf(v.x) + fabsf(v.y) + fabsf(v.z) + fabsf(v.w));
        float vv[8] = {u.x, u.y, u.z, u.w, v.x, v.y, v.z, v.w};
        unsigned b[8];
#pragma unroll
        for (int q = 0; q < 8; q++) b[q] = __ballot_sync(0xffffffffu, vv[q] > 0.f);
        if (L == 0) {
            g_mroot2[k] = s * (1.f / HID);
#pragma unroll
            for (int q = 0; q < 8; q++) g_wmask2[k * 8 + q] = b[q];
        }
    }
}

// ---------------- binact1 + hist (interleaved blocks) ----------------
// grid 33280: every 32nd block is a hist block (1040 of them covering E1+E2
// edges at 512 threads each); the rest are binact blocks (16 rows each).
#define BA_GRID 33280
__global__ __launch_bounds__(512) void binact1hist_kernel(
    const float* __restrict__ x, const int* __restrict__ dst1,
    const int* __restrict__ dst2)
{
    unsigned bid = blockIdx.x;
    if ((bid & 31u) == 0u) {
        unsigned i = (bid >> 5) * 512u + threadIdx.x;
        if (i < NE1) atomicAdd(&g_cnt1[dst1[i]], 1u);
        else {
            unsigned j = i - NE1;
            if (j < NE2) atomicAdd(&g_cnt2[dst2[j]], 1u);
        }
        return;
    }
    unsigned bb = bid - (bid >> 5) - 1u;
    if (bb >= 32000u) return;
    int row = bb * 16 + (threadIdx.x >> 5);
    int L = threadIdx.x & 31;
    float4 v = *(const float4*)(x + (size_t)row * IN_F + 4 * L);
    float s = v.x + v.y + v.z + v.w;
    float sq = fmaf(v.x, v.x, fmaf(v.y, v.y, fmaf(v.z, v.z, v.w * v.w)));
    s = warp_sum(s);
    sq = warp_sum(sq);
    float mu = s * (1.f / 128.f);
    float var = (sq - 128.f * mu * mu) * (1.f / 127.f);
    float sd = sqrtf(fmaxf(var, 0.f));
    float d0 = v.x - mu, d1 = v.y - mu, d2 = v.z - mu, d3 = v.w - mu;
    float l1 = warp_sum(fabsf(d0) + fabsf(d1) + fabsf(d2) + fabsf(d3));
    float a = (l1 * (1.f / 128.f)) / (sd + EPSV);
    unsigned b0 = __ballot_sync(0xffffffffu, d0 > 0.f);
    unsigned b1 = __ballot_sync(0xffffffffu, d1 > 0.f);
    unsigned b2 = __ballot_sync(0xffffffffu, d2 > 0.f);
    unsigned b3 = __ballot_sync(0xffffffffu, d3 > 0.f);
    if (L == 0) {
        g_alpha1[row] = a;
        g_mask1[row] = make_uint4(b0, b1, b2, b3);
    }
}

// ---------------- scan (both layers; block 0 -> layer1, block 1 -> layer2) --
__global__ __launch_bounds__(1024) void scan12_kernel() {
    int layer = blockIdx.x;
    const unsigned* cnt = layer ? g_cnt2 : g_cnt1;
    unsigned* off = layer ? g_off2 : g_off1;
    unsigned* cur = layer ? g_cur2 : g_cur1;
    int n = layer ? NN2 : NN1;
    int per = n >> 10;
    int t = threadIdx.x;
    int s0 = t * per;
    unsigned tot = 0;
    for (int i = 0; i < per; i++) tot += cnt[s0 + i];
    unsigned ws = tot;
#pragma unroll
    for (int o = 1; o < 32; o <<= 1) {
        unsigned u = __shfl_up_sync(0xffffffffu, ws, o);
        if ((t & 31) >= o) ws += u;
    }
    __shared__ unsigned wsum[32];
    if ((t & 31) == 31) wsum[t >> 5] = ws;
    __syncthreads();
    if (t < 32) {
        unsigned v2 = wsum[t];
        unsigned sc = v2;
#pragma unroll
        for (int o = 1; o < 32; o <<= 1) {
            unsigned u = __shfl_up_sync(0xffffffffu, sc, o);
            if (t >= o) sc += u;
        }
        wsum[t] = sc - v2;   // exclusive
    }
    __syncthreads();
    unsigned run = wsum[t >> 5] + ws - tot;
    for (int i = 0; i < per; i++) {
        unsigned c = cnt[s0 + i];
        off[s0 + i] = run;
        cur[s0 + i] = run;
        run += c;
    }
    if (t == 1023) off[n] = run;
}

// ---------------- placement (both layers) ----------------
__global__ __launch_bounds__(512) void place12_kernel(
    const int* __restrict__ dst1, const int* __restrict__ src1,
    const int* __restrict__ dst2, const int* __restrict__ src2)
{
    unsigned i = blockIdx.x * 512u + threadIdx.x;
    if (i < NE1) {
        unsigned p = atomicAdd(&g_cur1[dst1[i]], 1u);
        g_srcs1[p] = src1[i];
    } else {
        unsigned j = i - NE1;
        if (j < NE2) {
            unsigned p = atomicAdd(&g_cur2[dst2[j]], 1u);
            g_srcs2[p] = src2[j];
        }
    }
}

// ---------------- layer-1 aggregation: warp per dst, lane-parallel gather ---
__global__ __launch_bounds__(256) void agg1_kernel() {
    int d = (blockIdx.x * 256 + threadIdx.x) >> 5;
    if (d >= NN1) return;
    int L = threadIdx.x & 31;
    unsigned beg = g_off1[d], end = g_off1[d + 1];
    float a0 = 0.f, a1 = 0.f, a2 = 0.f, a3 = 0.f;
    for (unsigned base = beg; base < end; base += 32u) {
        unsigned e = base + L;
        float al = 0.f;
        uint4 m = make_uint4(0u, 0u, 0u, 0u);
        if (e < end) {
            int s = g_srcs1[e];
            al = g_alpha1[s];
            m = g_mask1[s];
        }
        unsigned n = min(32u, end - base);
        for (unsigned t = 0; t < n; t++) {
            float av = __shfl_sync(0xffffffffu, al, t);
            unsigned mx = __shfl_sync(0xffffffffu, m.x, t);
            unsigned my = __shfl_sync(0xffffffffu, m.y, t);
            unsigned mz = __shfl_sync(0xffffffffu, m.z, t);
            unsigned mw = __shfl_sync(0xffffffffu, m.w, t);
            a0 += ((mx >> L) & 1u) ? av : -av;
            a1 += ((my >> L) & 1u) ? av : -av;
            a2 += ((mz >> L) & 1u) ? av : -av;
            a3 += ((mw >> L) & 1u) ? av : -av;
        }
    }
    unsigned c = end - beg;
    float inv = 1.f / (float)(c == 0u ? 1u : c);
    *(float4*)(g_agg1 + (size_t)d * IN_F + 4 * L) =
        make_float4(a0 * inv, a1 * inv, a2 * inv, a3 * inv);
}

// ---------------- fused gemm1 + root + bias + relu + binact2 ----------------
// C[64 x 256] tile per block; 8 warps, warp w owns rows w*8..w*8+7,
// lane L owns cols 8L..8L+7. Never writes h to global: binact2 in epilogue.
#define GBM 64
#define GBK 16
__global__ __launch_bounds__(256, 2) void gemm1_fused_kernel() {
    __shared__ float As[GBK][72];          // k-major: As[kk][row]
    __shared__ float2 Bs[GBK][4][32];      // Bs[kk][j][lane] = cols (8*lane+2j, +1)
    int tid = threadIdx.x;
    int w = tid >> 5, L = tid & 31;
    int bm = blockIdx.x * GBM;
    unsigned long long acc[8][4];
#pragma unroll
    for (int i = 0; i < 8; i++)
#pragma unroll
        for (int j = 0; j < 4; j++) acc[i][j] = 0ull;

    for (int k0 = 0; k0 < IN_F; k0 += GBK) {
        {   // stage A (transpose to k-major): 64 rows x 16 k = 256 float4s
            int row = tid >> 2, kq = tid & 3;
            float4 v = *(const float4*)(g_agg1 + (size_t)(bm + row) * IN_F + k0 + 4 * kq);
            As[kq * 4 + 0][row] = v.x;
            As[kq * 4 + 1][row] = v.y;
            As[kq * 4 + 2][row] = v.z;
            As[kq * 4 + 3][row] = v.w;
        }
        {   // stage B: 16 k x 256 cols = 1024 float4s, pre-paired layout
#pragma unroll
            for (int r = 0; r < 4; r++) {
                int g = tid + r * 256;
                int kk = g >> 6, n4 = g & 63;
                float4 v = *(const float4*)(g_bt1 + (size_t)(k0 + kk) * HID + 4 * n4);
                int m = n4 >> 1, jb = (n4 & 1) * 2;
                Bs[kk][jb][m] = make_float2(v.x, v.y);
                Bs[kk][jb + 1][m] = make_float2(v.z, v.w);
            }
        }
        __syncthreads();
#pragma unroll
        for (int kk = 0; kk < GBK; kk++) {
            float4 a0 = *(const float4*)&As[kk][w * 8];
            float4 a1 = *(const float4*)&As[kk][w * 8 + 4];
            unsigned long long b[4];
#pragma unroll
            for (int j = 0; j < 4; j++)
                b[j] = *(const unsigned long long*)&Bs[kk][j][L];
            float av[8] = {a0.x, a0.y, a0.z, a0.w, a1.x, a1.y, a1.z, a1.w};
#pragma unroll
            for (int i = 0; i < 8; i++) {
                unsigned long long ad = bcast2(av[i]);
                fma2(acc[i][0], ad, b[0]);
                fma2(acc[i][1], ad, b[1]);
                fma2(acc[i][2], ad, b[2]);
                fma2(acc[i][3], ad, b[3]);
            }
        }
        __syncthreads();
    }

    // epilogue: per-lane col metadata (cols 8L+q)
    uint4 wm[8];
    float mr[8], bs[8];
#pragma unroll
    for (int q = 0; q < 8; q++) {
        wm[q] = g_wmask1[8 * L + q];
        mr[q] = g_mroot1[8 * L + q];
        bs[q] = g_bsum1[8 * L + q];
    }
#pragma unroll
    for (int i = 0; i < 8; i++) {
        int gm = bm + w * 8 + i;
        float al = g_alpha1[gm];
        uint4 mx = g_mask1[gm];
        float v[8];
#pragma unroll
        for (int j = 0; j < 4; j++) {
            float lo, hi;
            unpack2(acc[i][j], lo, hi);
            int p0 = popc4(mx, wm[2 * j]);
            int p1 = popc4(mx, wm[2 * j + 1]);
            v[2 * j]     = fmaxf(lo + bs[2 * j]     + al * mr[2 * j]     * (float)(128 - 2 * p0), 0.f);
            v[2 * j + 1] = fmaxf(hi + bs[2 * j + 1] + al * mr[2 * j + 1] * (float)(128 - 2 * p1), 0.f);
        }
        // binact2 over this row (256 values across warp)
        float s = 0.f, sq = 0.f;
#pragma unroll
        for (int q = 0; q < 8; q++) { s += v[q]; sq = fmaf(v[q], v[q], sq); }
        s = warp_sum(s);
        sq = warp_sum(sq);
        float mu = s * (1.f / 256.f);
        float var = (sq - 256.f * mu * mu) * (1.f / 255.f);
        float sd = sqrtf(fmaxf(var, 0.f));
        float l1 = 0.f;
#pragma unroll
        for (int q = 0; q < 8; q++) l1 += fabsf(v[q] - mu);
        l1 = warp_sum(l1);
        float a2v = (l1 * (1.f / 256.f)) / (sd + EPSV);
        unsigned b[8];
#pragma unroll
        for (int q = 0; q < 8; q++) b[q] = __ballot_sync(0xffffffffu, v[q] - mu > 0.f);
        if (L == 0) {
            g_alpha2[gm] = a2v;
            uint4* mp = (uint4*)(g_mask2 + (size_t)gm * 8);
            mp[0] = make_uint4(b[0], b[1], b[2], b[3]);
            mp[1] = make_uint4(b[4], b[5], b[6], b[7]);
        }
    }
}

// ---------------- fused agg2 + gemm2 + root + log_softmax ----------------
__global__ __launch_bounds__(256) void aggfinal_kernel(float* __restrict__ out) {
    __shared__ float sa[8][264];
    __shared__ float bts[64][72];
    int tid = threadIdx.x;
    int w = tid >> 5, L = tid & 31;
    int d = blockIdx.x * 8 + w;

    // aggregation (lane-parallel gather + shfl broadcast)
    unsigned beg = g_off2[d], end = g_off2[d + 1];
    float a[8];
#pragma unroll
    for (int q = 0; q < 8; q++) a[q] = 0.f;
    for (unsigned base = beg; base < end; base += 32u) {
        unsigned e = base + L;
        float al = 0.f;
        uint4 m1 = make_uint4(0u, 0u, 0u, 0u), m2 = m1;
        if (e < end) {
            int s = g_srcs2[e];
            al = g_alpha2[s];
            const uint4* mp = (const uint4*)(g_mask2 + (size_t)s * 8);
            m1 = mp[0]; m2 = mp[1];
        }
        unsigned n = min(32u, end - base);
        for (unsigned t = 0; t < n; t++) {
            float av = __shfl_sync(0xffffffffu, al, t);
            unsigned mw0 = __shfl_sync(0xffffffffu, m1.x, t);
            unsigned mw1 = __shfl_sync(0xffffffffu, m1.y, t);
            unsigned mw2 = __shfl_sync(0xffffffffu, m1.z, t);
            unsigned mw3 = __shfl_sync(0xffffffffu, m1.w, t);
            unsigned mw4 = __shfl_sync(0xffffffffu, m2.x, t);
            unsigned mw5 = __shfl_sync(0xffffffffu, m2.y, t);
            unsigned mw6 = __shfl_sync(0xffffffffu, m2.z, t);
            unsigned mw7 = __shfl_sync(0xffffffffu, m2.w, t);
            a[0] += ((mw0 >> L) & 1u) ? av : -av;
            a[1] += ((mw1 >> L) & 1u) ? av : -av;
            a[2] += ((mw2 >> L) & 1u) ? av : -av;
            a[3] += ((mw3 >> L) & 1u) ? av : -av;
            a[4] += ((mw4 >> L) & 1u) ? av : -av;
            a[5] += ((mw5 >> L) & 1u) ? av : -av;
            a[6] += ((mw6 >> L) & 1u) ? av : -av;
            a[7] += ((mw7 >> L) & 1u) ? av : -av;
        }
    }
    unsigned c = end - beg;
    float inv = 1.f / (float)(c == 0u ? 1u : c);
#pragma unroll
    for (int q = 0; q < 8; q++) sa[w][8 * L + q] = a[q] * inv;

    // GEMV with bt2 staged through smem (4 chunks of 64 rows)
    float acc0 = 0.f, acc1 = 0.f;
    for (int j0 = 0; j0 < HID; j0 += 64) {
        __syncthreads();
#pragma unroll
        for (int r = 0; r < 4; r++) {
            int f = tid + r * 256;
            int jj = f >> 4, c4 = f & 15;
            *(float4*)&bts[jj][c4 * 4] =
                *(const float4*)(g_bt2 + (size_t)(j0 + jj) * OUT_F + 4 * c4);
        }
        __syncthreads();
#pragma unroll 8
        for (int jj = 0; jj < 64; jj++) {
            float av = sa[w][j0 + jj];
            acc0 = fmaf(av, bts[jj][L], acc0);
            acc1 = fmaf(av, bts[jj][L + 32], acc1);
        }
    }

    // root + bias + log_softmax
    int c0 = L, c1 = L + 32;
    const uint4* mp = (const uint4*)(g_mask2 + (size_t)d * 8);
    uint4 ma = mp[0], mb = mp[1];
    float al = g_alpha2[d];
    const uint4* w0 = (const uint4*)(g_wmask2 + c0 * 8);
    const uint4* w1 = (const uint4*)(g_wmask2 + c1 * 8);
    int p0 = popc4(ma, w0[0]) + popc4(mb, w0[1]);
    int p1 = popc4(ma, w1[0]) + popc4(mb, w1[1]);
    float v0 = acc0 + g_bsum2[c0] + al * g_mroot2[c0] * (float)(256 - 2 * p0);
    float v1 = acc1 + g_bsum2[c1] + al * g_mroot2[c1] * (float)(256 - 2 * p1);
    float mx = warp_max(fmaxf(v0, v1));
    float s = warp_sum(expf(v0 - mx) + expf(v1 - mx));
    float lse = mx + logf(s);
    out[(size_t)d * OUT_F + c0] = v0 - lse;
    out[(size_t)d * OUT_F + c1] = v1 - lse;
}

// ---------------- launcher ----------------
extern "C" void kernel_launch(void* const* d_in, const int* in_sizes, int n_in,
                              void* d_out, int out_size) {
    const float* x       = (const float*)d_in[0];
    const int*   src1    = (const int*)d_in[1];
    const int*   dst1    = (const int*)d_in[2];
    const int*   src2    = (const int*)d_in[3];
    const int*   dst2    = (const int*)d_in[4];
    const float* w_rel1  = (const float*)d_in[5];
    const float* b_rel1  = (const float*)d_in[6];
    const float* w_root1 = (const float*)d_in[7];
    const float* b_root1 = (const float*)d_in[8];
    const float* w_rel2  = (const float*)d_in[9];
    const float* b_rel2  = (const float*)d_in[10];
    const float* w_root2 = (const float*)d_in[11];
    const float* b_root2 = (const float*)d_in[12];
    float* out = (float*)d_out;

    prep_zero<<<160, 128>>>(w_rel1, w_root1, w_rel2, w_root2,
                            b_rel1, b_root1, b_rel2, b_root2);
    binact1hist_kernel<<<BA_GRID, 512>>>(x, dst1, dst2);
    scan12_kernel<<<2, 1024>>>();
    place12_kernel<<<(NE1 + NE2 + 511) / 512, 512>>>(dst1, src1, dst2, src2);
    agg1_kernel<<<NN1 * 32 / 256, 256>>>();
    gemm1_fused_kernel<<<NN1 / GBM, 256>>>();
    aggfinal_kernel<<<NN2 / 8, 256>>>(out);
    (void)in_sizes; (void)n_in; (void)out_size;
}

// round 3
// speedup vs baseline: 1.1908x; 1.0045x over previous
#include <cuda_runtime.h>
#include <cstdint>

#define N0    512000
#define IN_F  128
#define HID   256
#define OUT_F 64
#define NN1   20480
#define NN2   2048
#define NE1   512000
#define NE2   20480
#define EPSV  1e-4f

// ---------------- device scratch ----------------
__device__ float    g_alpha1[N0];
__device__ uint4    g_mask1[N0];
__device__ unsigned g_cnt1[NN1];
__device__ unsigned g_off1[NN1 + 1];
__device__ unsigned g_cur1[NN1];
__device__ int      g_srcs1[NE1];
__device__ float    g_agg1[NN1 * IN_F];
__device__ float    g_alpha2[NN1];
__device__ unsigned g_mask2[NN1 * 8];
__device__ unsigned g_cnt2[NN2];
__device__ unsigned g_off2[NN2 + 1];
__device__ unsigned g_cur2[NN2];
__device__ int      g_srcs2[NE2];
__device__ float    g_bt1[IN_F * HID];    // w_hat_rel1 transposed: [k=128][n=256]
__device__ float    g_mroot1[HID];
__device__ uint4    g_wmask1[HID];
__device__ float    g_bsum1[HID];
__device__ float    g_bt2[HID * OUT_F];   // [256][64]
__device__ float    g_mroot2[OUT_F];
__device__ unsigned g_wmask2[OUT_F * 8];
__device__ float    g_bsum2[OUT_F];

// ---------------- helpers ----------------
__device__ __forceinline__ float warp_sum(float v) {
#pragma unroll
    for (int o = 16; o; o >>= 1) v += __shfl_xor_sync(0xffffffffu, v, o);
    return v;
}
__device__ __forceinline__ float warp_max(float v) {
#pragma unroll
    for (int o = 16; o; o >>= 1) v = fmaxf(v, __shfl_xor_sync(0xffffffffu, v, o));
    return v;
}
__device__ __forceinline__ unsigned long long bcast2(float a) {
    unsigned long long r;
    asm("mov.b64 %0, {%1, %1};" : "=l"(r) : "f"(a));
    return r;
}
__device__ __forceinline__ void fma2(unsigned long long& c, unsigned long long a, unsigned long long b) {
    asm("fma.rn.f32x2 %0, %1, %2, %0;" : "+l"(c) : "l"(a), "l"(b));
}
__device__ __forceinline__ void unpack2(unsigned long long v, float& lo, float& hi) {
    asm("mov.b64 {%0, %1}, %2;" : "=f"(lo), "=f"(hi) : "l"(v));
}
__device__ __forceinline__ int popc4(uint4 a, uint4 b) {
    return __popc(a.x ^ b.x) + __popc(a.y ^ b.y) + __popc(a.z ^ b.z) + __popc(a.w ^ b.w);
}

// ---------------- weight prep + counter zero + bias sums ----------------
// 160 blocks x 128 threads = 20480 threads = 640 warps.
__global__ __launch_bounds__(128) void prep_zero(
    const float* __restrict__ wr1, const float* __restrict__ wroot1,
    const float* __restrict__ wr2, const float* __restrict__ wroot2,
    const float* __restrict__ brel1, const float* __restrict__ broot1,
    const float* __restrict__ brel2, const float* __restrict__ broot2)
{
    int t = blockIdx.x * 128 + threadIdx.x;   // 0..20479
    g_cnt1[t] = 0u;
    if (t < NN2) g_cnt2[t] = 0u;
    if (t < HID) g_bsum1[t] = brel1[t] + broot1[t];
    if (t < OUT_F) g_bsum2[t] = brel2[t] + broot2[t];

    int w = t >> 5;
    int L = threadIdx.x & 31;
    if (w < HID) {
        int k = w;
        float4 v = *(const float4*)(wr1 + (size_t)k * IN_F + 4 * L);
        float s = warp_sum(fabsf(v.x) + fabsf(v.y) + fabsf(v.z) + fabsf(v.w));
        float m = s * (1.f / IN_F);
        float vv[4] = {v.x, v.y, v.z, v.w};
#pragma unroll
        for (int q = 0; q < 4; q++) {
            int j = 4 * L + q;
            float val = vv[q] > 0.f ? m : (vv[q] < 0.f ? -m : 0.f);
            g_bt1[j * HID + k] = val;
        }
    } else if (w < 2 * HID) {
        int k = w - HID;
        float4 v = *(const float4*)(wroot1 + (size_t)k * IN_F + 4 * L);
        float s = warp_sum(fabsf(v.x) + fabsf(v.y) + fabsf(v.z) + fabsf(v.w));
        unsigned b0 = __ballot_sync(0xffffffffu, v.x > 0.f);
        unsigned b1 = __ballot_sync(0xffffffffu, v.y > 0.f);
        unsigned b2 = __ballot_sync(0xffffffffu, v.z > 0.f);
        unsigned b3 = __ballot_sync(0xffffffffu, v.w > 0.f);
        if (L == 0) {
            g_mroot1[k] = s * (1.f / IN_F);
            g_wmask1[k] = make_uint4(b0, b1, b2, b3);
        }
    } else if (w < 2 * HID + OUT_F) {
        int k = w - 2 * HID;
        float4 u = *(const float4*)(wr2 + (size_t)k * HID + 8 * L);
        float4 v = *(const float4*)(wr2 + (size_t)k * HID + 8 * L + 4);
        float s = warp_sum(fabsf(u.x) + fabsf(u.y) + fabsf(u.z) + fabsf(u.w) +
                           fabsf(v.x) + fabsf(v.y) + fabsf(v.z) + fabsf(v.w));
        float m = s * (1.f / HID);
        float vv[8] = {u.x, u.y, u.z, u.w, v.x, v.y, v.z, v.w};
#pragma unroll
        for (int q = 0; q < 8; q++) {
            int j = 8 * L + q;
            float val = vv[q] > 0.f ? m : (vv[q] < 0.f ? -m : 0.f);
            g_bt2[j * OUT_F + k] = val;
        }
    } else if (w < 2 * HID + 2 * OUT_F) {
        int k = w - 2 * HID - OUT_F;
        float4 u = *(const float4*)(wroot2 + (size_t)k * HID + 8 * L);
        float4 v = *(const float4*)(wroot2 + (size_t)k * HID + 8 * L + 4);
        float s = warp_sum(fabsf(u.x) + fabsf(u.y) + fabsf(u.z) + fabsf(u.w) +
                           fabsf(v.x) + fabsf(v.y) + fabsf(v.z) + fabsf(v.w));
        float vv[8] = {u.x, u.y, u.z, u.w, v.x, v.y, v.z, v.w};
        unsigned b[8];
#pragma unroll
        for (int q = 0; q < 8; q++) b[q] = __ballot_sync(0xffffffffu, vv[q] > 0.f);
        if (L == 0) {
            g_mroot2[k] = s * (1.f / HID);
#pragma unroll
            for (int q = 0; q < 8; q++) g_wmask2[k * 8 + q] = b[q];
        }
    }
}

// ---------------- binact1 + hist (interleaved blocks) ----------------
// grid 33280: every 32nd block is a hist block (1040 of them covering E1+E2
// edges at 512 threads each); the rest are binact blocks (16 rows each).
#define BA_GRID 33280
__global__ __launch_bounds__(512) void binact1hist_kernel(
    const float* __restrict__ x, const int* __restrict__ dst1,
    const int* __restrict__ dst2)
{
    unsigned bid = blockIdx.x;
    if ((bid & 31u) == 0u) {
        unsigned i = (bid >> 5) * 512u + threadIdx.x;
        if (i < NE1) atomicAdd(&g_cnt1[dst1[i]], 1u);
        else {
            unsigned j = i - NE1;
            if (j < NE2) atomicAdd(&g_cnt2[dst2[j]], 1u);
        }
        return;
    }
    unsigned bb = bid - (bid >> 5) - 1u;
    if (bb >= 32000u) return;
    int row = bb * 16 + (threadIdx.x >> 5);
    int L = threadIdx.x & 31;
    float4 v = *(const float4*)(x + (size_t)row * IN_F + 4 * L);
    float s = v.x + v.y + v.z + v.w;
    float sq = fmaf(v.x, v.x, fmaf(v.y, v.y, fmaf(v.z, v.z, v.w * v.w)));
    s = warp_sum(s);
    sq = warp_sum(sq);
    float mu = s * (1.f / 128.f);
    float var = (sq - 128.f * mu * mu) * (1.f / 127.f);
    float sd = sqrtf(fmaxf(var, 0.f));
    float d0 = v.x - mu, d1 = v.y - mu, d2 = v.z - mu, d3 = v.w - mu;
    float l1 = warp_sum(fabsf(d0) + fabsf(d1) + fabsf(d2) + fabsf(d3));
    float a = (l1 * (1.f / 128.f)) / (sd + EPSV);
    unsigned b0 = __ballot_sync(0xffffffffu, d0 > 0.f);
    unsigned b1 = __ballot_sync(0xffffffffu, d1 > 0.f);
    unsigned b2 = __ballot_sync(0xffffffffu, d2 > 0.f);
    unsigned b3 = __ballot_sync(0xffffffffu, d3 > 0.f);
    if (L == 0) {
        g_alpha1[row] = a;
        g_mask1[row] = make_uint4(b0, b1, b2, b3);
    }
}

// ---------------- scan (both layers; block 0 -> layer1, block 1 -> layer2) --
__global__ __launch_bounds__(1024) void scan12_kernel() {
    int layer = blockIdx.x;
    const unsigned* cnt = layer ? g_cnt2 : g_cnt1;
    unsigned* off = layer ? g_off2 : g_off1;
    unsigned* cur = layer ? g_cur2 : g_cur1;
    int n = layer ? NN2 : NN1;
    int per = n >> 10;
    int t = threadIdx.x;
    int s0 = t * per;
    unsigned tot = 0;
    for (int i = 0; i < per; i++) tot += cnt[s0 + i];
    unsigned ws = tot;
#pragma unroll
    for (int o = 1; o < 32; o <<= 1) {
        unsigned u = __shfl_up_sync(0xffffffffu, ws, o);
        if ((t & 31) >= o) ws += u;
    }
    __shared__ unsigned wsum[32];
    if ((t & 31) == 31) wsum[t >> 5] = ws;
    __syncthreads();
    if (t < 32) {
        unsigned v2 = wsum[t];
        unsigned sc = v2;
#pragma unroll
        for (int o = 1; o < 32; o <<= 1) {
            unsigned u = __shfl_up_sync(0xffffffffu, sc, o);
            if (t >= o) sc += u;
        }
        wsum[t] = sc - v2;   // exclusive
    }
    __syncthreads();
    unsigned run = wsum[t >> 5] + ws - tot;
    for (int i = 0; i < per; i++) {
        unsigned c = cnt[s0 + i];
        off[s0 + i] = run;
        cur[s0 + i] = run;
        run += c;
    }
    if (t == 1023) off[n] = run;
}

// ---------------- placement (both layers) ----------------
__global__ __launch_bounds__(512) void place12_kernel(
    const int* __restrict__ dst1, const int* __restrict__ src1,
    const int* __restrict__ dst2, const int* __restrict__ src2)
{
    unsigned i = blockIdx.x * 512u + threadIdx.x;
    if (i < NE1) {
        unsigned p = atomicAdd(&g_cur1[dst1[i]], 1u);
        g_srcs1[p] = src1[i];
    } else {
        unsigned j = i - NE1;
        if (j < NE2) {
            unsigned p = atomicAdd(&g_cur2[dst2[j]], 1u);
            g_srcs2[p] = src2[j];
        }
    }
}

// ---------------- layer-1 aggregation: warp per dst, lane-parallel gather ---
__global__ __launch_bounds__(256) void agg1_kernel() {
    int d = (blockIdx.x * 256 + threadIdx.x) >> 5;
    if (d >= NN1) return;
    int L = threadIdx.x & 31;
    unsigned beg = g_off1[d], end = g_off1[d + 1];
    float a0 = 0.f, a1 = 0.f, a2 = 0.f, a3 = 0.f;
    for (unsigned base = beg; base < end; base += 32u) {
        unsigned e = base + L;
        float al = 0.f;
        uint4 m = make_uint4(0u, 0u, 0u, 0u);
        if (e < end) {
            int s = g_srcs1[e];
            al = g_alpha1[s];
            m = g_mask1[s];
        }
        unsigned n = min(32u, end - base);
        for (unsigned t = 0; t < n; t++) {
            float av = __shfl_sync(0xffffffffu, al, t);
            unsigned mx = __shfl_sync(0xffffffffu, m.x, t);
            unsigned my = __shfl_sync(0xffffffffu, m.y, t);
            unsigned mz = __shfl_sync(0xffffffffu, m.z, t);
            unsigned mw = __shfl_sync(0xffffffffu, m.w, t);
            a0 += ((mx >> L) & 1u) ? av : -av;
            a1 += ((my >> L) & 1u) ? av : -av;
            a2 += ((mz >> L) & 1u) ? av : -av;
            a3 += ((mw >> L) & 1u) ? av : -av;
        }
    }
    unsigned c = end - beg;
    float inv = 1.f / (float)(c == 0u ? 1u : c);
    *(float4*)(g_agg1 + (size_t)d * IN_F + 4 * L) =
        make_float4(a0 * inv, a1 * inv, a2 * inv, a3 * inv);
}

// ---------------- fused gemm1 + root + bias + relu + binact2 ----------------
// C[64 x 256] tile per block; 8 warps, warp w owns rows w*8..w*8+7,
// lane L owns cols 8L..8L+7. Never writes h to global: binact2 in epilogue.
#define GBM 64
#define GBK 16
__global__ __launch_bounds__(256, 2) void gemm1_fused_kernel() {
    __shared__ float As[GBK][72];          // k-major: As[kk][row]
    __shared__ float2 Bs[GBK][4][32];      // Bs[kk][j][lane] = cols (8*lane+2j, +1)
    int tid = threadIdx.x;
    int w = tid >> 5, L = tid & 31;
    int bm = blockIdx.x * GBM;
    unsigned long long acc[8][4];
#pragma unroll
    for (int i = 0; i < 8; i++)
#pragma unroll
        for (int j = 0; j < 4; j++) acc[i][j] = 0ull;

    for (int k0 = 0; k0 < IN_F; k0 += GBK) {
        {   // stage A (transpose to k-major): 64 rows x 16 k = 256 float4s
            int row = tid >> 2, kq = tid & 3;
            float4 v = *(const float4*)(g_agg1 + (size_t)(bm + row) * IN_F + k0 + 4 * kq);
            As[kq * 4 + 0][row] = v.x;
            As[kq * 4 + 1][row] = v.y;
            As[kq * 4 + 2][row] = v.z;
            As[kq * 4 + 3][row] = v.w;
        }
        {   // stage B: 16 k x 256 cols = 1024 float4s, pre-paired layout
#pragma unroll
            for (int r = 0; r < 4; r++) {
                int g = tid + r * 256;
                int kk = g >> 6, n4 = g & 63;
                float4 v = *(const float4*)(g_bt1 + (size_t)(k0 + kk) * HID + 4 * n4);
                int m = n4 >> 1, jb = (n4 & 1) * 2;
                Bs[kk][jb][m] = make_float2(v.x, v.y);
                Bs[kk][jb + 1][m] = make_float2(v.z, v.w);
            }
        }
        __syncthreads();
#pragma unroll
        for (int kk = 0; kk < GBK; kk++) {
            float4 a0 = *(const float4*)&As[kk][w * 8];
            float4 a1 = *(const float4*)&As[kk][w * 8 + 4];
            unsigned long long b[4];
#pragma unroll
            for (int j = 0; j < 4; j++)
                b[j] = *(const unsigned long long*)&Bs[kk][j][L];
            float av[8] = {a0.x, a0.y, a0.z, a0.w, a1.x, a1.y, a1.z, a1.w};
#pragma unroll
            for (int i = 0; i < 8; i++) {
                unsigned long long ad = bcast2(av[i]);
                fma2(acc[i][0], ad, b[0]);
                fma2(acc[i][1], ad, b[1]);
                fma2(acc[i][2], ad, b[2]);
                fma2(acc[i][3], ad, b[3]);
            }
        }
        __syncthreads();
    }

    // epilogue: per-lane col metadata (cols 8L+q)
    uint4 wm[8];
    float mr[8], bs[8];
#pragma unroll
    for (int q = 0; q < 8; q++) {
        wm[q] = g_wmask1[8 * L + q];
        mr[q] = g_mroot1[8 * L + q];
        bs[q] = g_bsum1[8 * L + q];
    }
#pragma unroll
    for (int i = 0; i < 8; i++) {
        int gm = bm + w * 8 + i;
        float al = g_alpha1[gm];
        uint4 mx = g_mask1[gm];
        float v[8];
#pragma unroll
        for (int j = 0; j < 4; j++) {
            float lo, hi;
            unpack2(acc[i][j], lo, hi);
            int p0 = popc4(mx, wm[2 * j]);
            int p1 = popc4(mx, wm[2 * j + 1]);
            v[2 * j]     = fmaxf(lo + bs[2 * j]     + al * mr[2 * j]     * (float)(128 - 2 * p0), 0.f);
            v[2 * j + 1] = fmaxf(hi + bs[2 * j + 1] + al * mr[2 * j + 1] * (float)(128 - 2 * p1), 0.f);
        }
        // binact2 over this row (256 values across warp)
        float s = 0.f, sq = 0.f;
#pragma unroll
        for (int q = 0; q < 8; q++) { s += v[q]; sq = fmaf(v[q], v[q], sq); }
        s = warp_sum(s);
        sq = warp_sum(sq);
        float mu = s * (1.f / 256.f);
        float var = (sq - 256.f * mu * mu) * (1.f / 255.f);
        float sd = sqrtf(fmaxf(var, 0.f));
        float l1 = 0.f;
#pragma unroll
        for (int q = 0; q < 8; q++) l1 += fabsf(v[q] - mu);
        l1 = warp_sum(l1);
        float a2v = (l1 * (1.f / 256.f)) / (sd + EPSV);
        unsigned b[8];
#pragma unroll
        for (int q = 0; q < 8; q++) b[q] = __ballot_sync(0xffffffffu, v[q] - mu > 0.f);
        if (L == 0) {
            g_alpha2[gm] = a2v;
            uint4* mp = (uint4*)(g_mask2 + (size_t)gm * 8);
            mp[0] = make_uint4(b[0], b[1], b[2], b[3]);
            mp[1] = make_uint4(b[4], b[5], b[6], b[7]);
        }
    }
}

// ---------------- fused agg2 + gemm2 + root + log_softmax ----------------
__global__ __launch_bounds__(256) void aggfinal_kernel(float* __restrict__ out) {
    __shared__ float sa[8][264];
    __shared__ float bts[64][72];
    int tid = threadIdx.x;
    int w = tid >> 5, L = tid & 31;
    int d = blockIdx.x * 8 + w;

    // aggregation (lane-parallel gather + shfl broadcast)
    unsigned beg = g_off2[d], end = g_off2[d + 1];
    float a[8];
#pragma unroll
    for (int q = 0; q < 8; q++) a[q] = 0.f;
    for (unsigned base = beg; base < end; base += 32u) {
        unsigned e = base + L;
        float al = 0.f;
        uint4 m1 = make_uint4(0u, 0u, 0u, 0u), m2 = m1;
        if (e < end) {
            int s = g_srcs2[e];
            al = g_alpha2[s];
            const uint4* mp = (const uint4*)(g_mask2 + (size_t)s * 8);
            m1 = mp[0]; m2 = mp[1];
        }
        unsigned n = min(32u, end - base);
        for (unsigned t = 0; t < n; t++) {
            float av = __shfl_sync(0xffffffffu, al, t);
            unsigned mw0 = __shfl_sync(0xffffffffu, m1.x, t);
            unsigned mw1 = __shfl_sync(0xffffffffu, m1.y, t);
            unsigned mw2 = __shfl_sync(0xffffffffu, m1.z, t);
            unsigned mw3 = __shfl_sync(0xffffffffu, m1.w, t);
            unsigned mw4 = __shfl_sync(0xffffffffu, m2.x, t);
            unsigned mw5 = __shfl_sync(0xffffffffu, m2.y, t);
            unsigned mw6 = __shfl_sync(0xffffffffu, m2.z, t);
            unsigned mw7 = __shfl_sync(0xffffffffu, m2.w, t);
            a[0] += ((mw0 >> L) & 1u) ? av : -av;
            a[1] += ((mw1 >> L) & 1u) ? av : -av;
            a[2] += ((mw2 >> L) & 1u) ? av : -av;
            a[3] += ((mw3 >> L) & 1u) ? av : -av;
            a[4] += ((mw4 >> L) & 1u) ? av : -av;
            a[5] += ((mw5 >> L) & 1u) ? av : -av;
            a[6] += ((mw6 >> L) & 1u) ? av : -av;
            a[7] += ((mw7 >> L) & 1u) ? av : -av;
        }
    }
    unsigned c = end - beg;
    float inv = 1.f / (float)(c == 0u ? 1u : c);
#pragma unroll
    for (int q = 0; q < 8; q++) sa[w][8 * L + q] = a[q] * inv;

    // GEMV with bt2 staged through smem (4 chunks of 64 rows)
    float acc0 = 0.f, acc1 = 0.f;
    for (int j0 = 0; j0 < HID; j0 += 64) {
        __syncthreads();
#pragma unroll
        for (int r = 0; r < 4; r++) {
            int f = tid + r * 256;
            int jj = f >> 4, c4 = f & 15;
            *(float4*)&bts[jj][c4 * 4] =
                *(const float4*)(g_bt2 + (size_t)(j0 + jj) * OUT_F + 4 * c4);
        }
        __syncthreads();
#pragma unroll 8
        for (int jj = 0; jj < 64; jj++) {
            float av = sa[w][j0 + jj];
            acc0 = fmaf(av, bts[jj][L], acc0);
            acc1 = fmaf(av, bts[jj][L + 32], acc1);
        }
    }

    // root + bias + log_softmax
    int c0 = L, c1 = L + 32;
    const uint4* mp = (const uint4*)(g_mask2 + (size_t)d * 8);
    uint4 ma = mp[0], mb = mp[1];
    float al = g_alpha2[d];
    const uint4* w0 = (const uint4*)(g_wmask2 + c0 * 8);
    const uint4* w1 = (const uint4*)(g_wmask2 + c1 * 8);
    int p0 = popc4(ma, w0[0]) + popc4(mb, w0[1]);
    int p1 = popc4(ma, w1[0]) + popc4(mb, w1[1]);
    float v0 = acc0 + g_bsum2[c0] + al * g_mroot2[c0] * (float)(256 - 2 * p0);
    float v1 = acc1 + g_bsum2[c1] + al * g_mroot2[c1] * (float)(256 - 2 * p1);
    float mx = warp_max(fmaxf(v0, v1));
    float s = warp_sum(expf(v0 - mx) + expf(v1 - mx));
    float lse = mx + logf(s);
    out[(size_t)d * OUT_F + c0] = v0 - lse;
    out[(size_t)d * OUT_F + c1] = v1 - lse;
}

// ---------------- launcher ----------------
extern "C" void kernel_launch(void* const* d_in, const int* in_sizes, int n_in,
                              void* d_out, int out_size) {
    const float* x       = (const float*)d_in[0];
    const int*   src1    = (const int*)d_in[1];
    const int*   dst1    = (const int*)d_in[2];
    const int*   src2    = (const int*)d_in[3];
    const int*   dst2    = (const int*)d_in[4];
    const float* w_rel1  = (const float*)d_in[5];
    const float* b_rel1  = (const float*)d_in[6];
    const float* w_root1 = (const float*)d_in[7];
    const float* b_root1 = (const float*)d_in[8];
    const float* w_rel2  = (const float*)d_in[9];
    const float* b_rel2  = (const float*)d_in[10];
    const float* w_root2 = (const float*)d_in[11];
    const float* b_root2 = (const float*)d_in[12];
    float* out = (float*)d_out;

    prep_zero<<<160, 128>>>(w_rel1, w_root1, w_rel2, w_root2,
                            b_rel1, b_root1, b_rel2, b_root2);
    binact1hist_kernel<<<BA_GRID, 512>>>(x, dst1, dst2);
    scan12_kernel<<<2, 1024>>>();
    place12_kernel<<<(NE1 + NE2 + 511) / 512, 512>>>(dst1, src1, dst2, src2);
    agg1_kernel<<<NN1 * 32 / 256, 256>>>();
    gemm1_fused_kernel<<<NN1 / GBM, 256>>>();
    aggfinal_kernel<<<NN2 / 8, 256>>>(out);
    (void)in_sizes; (void)n_in; (void)out_size;
}